// round 1
// baseline (speedup 1.0000x reference)
#include <cuda_runtime.h>

#define NB 64
#define NC 3
#define NH 96
#define NW 320
#define NHW (NH*NW)
#define K_TOP 50
#define CAND_CAP 5120
#define DET_TH 0.25f
#define PI_F 3.14159265f

// scratch (device globals: no allocation allowed)
__device__ float g_vals[NB*NC*K_TOP];
__device__ int   g_inds[NB*NC*K_TOP];
__device__ float g_score[NB*K_TOP];
__device__ int   g_hw[NB*K_TOP];
__device__ int   g_cls[NB*K_TOP];

// ---------------------------------------------------------------------------
// Kernel 1: 3x3 NMS + top-50 per (batch, channel).
// One CTA per channel. Survivors (local maxima, hmax==heat) are collected
// into shared memory, then 50 rounds of block-wide argmax with lax.top_k
// tie-break semantics (value desc, index asc).
// ---------------------------------------------------------------------------
__global__ __launch_bounds__(256) void nms_topk_kernel(const float* __restrict__ heat) {
    __shared__ float cv[CAND_CAP];
    __shared__ int   ci[CAND_CAP];
    __shared__ float rv[256];
    __shared__ int   ri[256];
    __shared__ int   rp[256];
    __shared__ int   cnt;

    const int bc = blockIdx.x;                 // b*NC + c
    const float* __restrict__ h = heat + (size_t)bc * NHW;
    const int t = threadIdx.x;

    if (t == 0) cnt = 0;
    __syncthreads();

    for (int idx = t; idx < NHW; idx += blockDim.x) {
        int y = idx / NW;
        int x = idx - y * NW;
        float v = __ldg(h + idx);
        int y0 = y > 0 ? y - 1 : 0;
        int y1 = y < NH - 1 ? y + 1 : NH - 1;
        int x0 = x > 0 ? x - 1 : 0;
        int x1 = x < NW - 1 ? x + 1 : NW - 1;
        float m = v;
        for (int yy = y0; yy <= y1; yy++) {
            const float* row = h + yy * NW;
            for (int xx = x0; xx <= x1; xx++) m = fmaxf(m, __ldg(row + xx));
        }
        if (v == m) {   // survives NMS (ties on plateaus all survive, same as ref)
            int p = atomicAdd(&cnt, 1);
            if (p < CAND_CAP) { cv[p] = v; ci[p] = idx; }
        }
    }
    __syncthreads();

    int n = cnt < CAND_CAP ? cnt : CAND_CAP;

    for (int k = 0; k < K_TOP; k++) {
        float bv = -1e30f; int bi = 0x7fffffff; int bp = -1;
        for (int j = t; j < n; j += blockDim.x) {
            float v = cv[j];
            int id = ci[j];
            if (v > bv || (v == bv && id < bi)) { bv = v; bi = id; bp = j; }
        }
        rv[t] = bv; ri[t] = bi; rp[t] = bp;
        __syncthreads();
        for (int s = 128; s > 0; s >>= 1) {
            if (t < s) {
                float v2 = rv[t + s]; int i2 = ri[t + s];
                if (v2 > rv[t] || (v2 == rv[t] && i2 < ri[t])) {
                    rv[t] = v2; ri[t] = i2; rp[t] = rp[t + s];
                }
            }
            __syncthreads();
        }
        if (t == 0) {
            float v = rv[0]; int id = ri[0];
            if (rp[0] < 0 || v < -1e29f) { v = 0.0f; id = 0; }  // <50 survivors: ref picks zeros; rows fail keep anyway
            else cv[rp[0]] = -1e30f;                             // remove winner
            g_vals[bc * K_TOP + k] = v;
            g_inds[bc * K_TOP + k] = id;
        }
        __syncthreads();
    }
}

// ---------------------------------------------------------------------------
// Kernel 2: per-batch merge of 3 sorted (desc) channel lists into top-50.
// Tie-break = lower flat index in the (C*TOPK) array = lower channel first.
// ---------------------------------------------------------------------------
__global__ void merge_kernel() {
    int b = blockIdx.x * blockDim.x + threadIdx.x;
    if (b >= NB) return;
    int j0 = 0, j1 = 0, j2 = 0;
    const float* base = g_vals + b * NC * K_TOP;
    const int*  ibase = g_inds + b * NC * K_TOP;
    for (int k = 0; k < K_TOP; k++) {
        float v0 = (j0 < K_TOP) ? base[0 * K_TOP + j0] : -1e30f;
        float v1 = (j1 < K_TOP) ? base[1 * K_TOP + j1] : -1e30f;
        float v2 = (j2 < K_TOP) ? base[2 * K_TOP + j2] : -1e30f;
        int c = 0; float bv = v0;
        if (v1 > bv) { bv = v1; c = 1; }   // strict >: equal values keep lower channel
        if (v2 > bv) { bv = v2; c = 2; }
        int jc = (c == 0) ? j0 : (c == 1 ? j1 : j2);
        g_score[b * K_TOP + k] = bv;
        g_cls[b * K_TOP + k] = c;
        g_hw[b * K_TOP + k] = ibase[c * K_TOP + jc];
        if (c == 0) j0++; else if (c == 1) j1++; else j2++;
    }
}

// ---------------------------------------------------------------------------
// Kernel 3: per-detection geometry (3200 threads).
// ---------------------------------------------------------------------------
__device__ __forceinline__ void inv3(const float* __restrict__ A, float* Ai) {
    float a = A[0], b = A[1], c = A[2];
    float d = A[3], e = A[4], f = A[5];
    float g = A[6], h = A[7], i = A[8];
    float A00 = e * i - f * h, A01 = c * h - b * i, A02 = b * f - c * e;
    float A10 = f * g - d * i, A11 = a * i - c * g, A12 = c * d - a * f;
    float A20 = d * h - e * g, A21 = b * g - a * h, A22 = a * e - b * d;
    float r = 1.0f / (a * A00 + b * A10 + c * A20);
    Ai[0] = A00 * r; Ai[1] = A01 * r; Ai[2] = A02 * r;
    Ai[3] = A10 * r; Ai[4] = A11 * r; Ai[5] = A12 * r;
    Ai[6] = A20 * r; Ai[7] = A21 * r; Ai[8] = A22 * r;
}

__device__ __forceinline__ float wrap_pi(float a) {
    return a > PI_F ? a - 2.0f * PI_F : (a < -PI_F ? a + 2.0f * PI_F : a);
}

__global__ void geom_kernel(const float* __restrict__ regr,
                            const float* __restrict__ calib,
                            const float* __restrict__ trans,
                            const float* __restrict__ dimref,
                            float* __restrict__ out) {
    int det = blockIdx.x * blockDim.x + threadIdx.x;
    if (det >= NB * K_TOP) return;
    int b = det / K_TOP;
    float score = g_score[det];
    float* o = out + (size_t)det * 14;

    if (!(score > DET_TH)) {
        #pragma unroll
        for (int i = 0; i < 14; i++) o[i] = 0.0f;
        return;
    }

    int hw = g_hw[det];
    int cls = g_cls[det];
    float xs = (float)(hw % NW);
    float ys = (float)(hw / NW);

    float reg[12];
    const float* rb = regr + ((size_t)b * 12) * NHW + hw;
    #pragma unroll
    for (int r = 0; r < 12; r++) reg[r] = __ldg(rb + r * NHW);

    float Ti[9], Ki[9];
    float Tm[9], Km[9];
    #pragma unroll
    for (int i = 0; i < 9; i++) { Tm[i] = __ldg(trans + b * 9 + i); Km[i] = __ldg(calib + b * 9 + i); }
    inv3(Tm, Ti);
    inv3(Km, Ki);

    float depth = reg[0] * 16.32f + 28.01f;
    float px = xs + reg[1], py = ys + reg[2];
    float t0 = (Ti[0] * px + Ti[1] * py + Ti[2]) * depth;
    float t1 = (Ti[3] * px + Ti[4] * py + Ti[5]) * depth;
    float t2 = (Ti[6] * px + Ti[7] * py + Ti[8]) * depth;
    float l0 = Ki[0] * t0 + Ki[1] * t1 + Ki[2] * t2;
    float l1 = Ki[3] * t0 + Ki[4] * t1 + Ki[5] * t2;
    float l2 = Ki[6] * t0 + Ki[7] * t1 + Ki[8] * t2;

    float d0 = expf(reg[3]) * __ldg(dimref + cls * 3 + 0);
    float d1 = expf(reg[4]) * __ldg(dimref + cls * 3 + 1);
    float d2 = expf(reg[5]) * __ldg(dimref + cls * 3 + 2);
    l1 += d1 * 0.5f;

    float ray = atanf(l0 / (l2 + 1e-7f));
    float alpha = atanf(reg[6] / (reg[7] + 1e-7f));
    alpha += (reg[7] >= 0.0f) ? -PI_F * 0.5f : PI_F * 0.5f;
    float roty = wrap_pi(alpha + ray);   // uses pre-wrap alpha, per ref
    alpha = wrap_pi(alpha);

    float cx = xs + reg[8], cy = ys + reg[9];
    float ltx = cx - reg[10] * 0.5f, lty = cy - reg[11] * 0.5f;
    float rbx = cx + reg[10] * 0.5f, rby = cy + reg[11] * 0.5f;
    float b0 = Ti[0] * ltx + Ti[1] * lty + Ti[2];
    float b1 = Ti[3] * ltx + Ti[4] * lty + Ti[5];
    float b2 = Ti[0] * rbx + Ti[1] * rby + Ti[2];
    float b3 = Ti[3] * rbx + Ti[4] * rby + Ti[5];

    o[0] = (float)cls;
    o[1] = alpha;
    o[2] = b0; o[3] = b1; o[4] = b2; o[5] = b3;
    o[6] = d1; o[7] = d2; o[8] = d0;       // roll(dims3d, -1)
    o[9] = l0; o[10] = l1; o[11] = l2;
    o[12] = roty;
    o[13] = score;
}

// ---------------------------------------------------------------------------
extern "C" void kernel_launch(void* const* d_in, const int* in_sizes, int n_in,
                              void* d_out, int out_size) {
    const float* heat   = (const float*)d_in[0];
    const float* regr   = (const float*)d_in[1];
    const float* calib  = (const float*)d_in[2];
    const float* trans  = (const float*)d_in[3];
    const float* dimref = (const float*)d_in[4];
    float* out = (float*)d_out;

    nms_topk_kernel<<<NB * NC, 256>>>(heat);
    merge_kernel<<<1, 64>>>();
    geom_kernel<<<(NB * K_TOP + 127) / 128, 128>>>(regr, calib, trans, dimref, out);
}

// round 2
// speedup vs baseline: 2.7194x; 2.7194x over previous
#include <cuda_runtime.h>

#define NB 64
#define NC 3
#define NH 96
#define NW 320
#define NHW (NH*NW)
#define K_TOP 50
#define CAND_CAP 4864
#define SBUF 512
#define DET_TH 0.25f
#define PI_F 3.14159265f
#define NITEMS (NH*(NW/8))   // 3840 items of 8 pixels

__device__ float g_vals[NB*NC*K_TOP];
__device__ int   g_inds[NB*NC*K_TOP];

// order-preserving float<->uint key (ascending float -> ascending uint)
__device__ __forceinline__ unsigned f2k(float f){
    unsigned b = __float_as_uint(f);
    return (b & 0x80000000u) ? ~b : (b | 0x80000000u);
}
__device__ __forceinline__ float k2f(unsigned k){
    return (k & 0x80000000u) ? __uint_as_float(k ^ 0x80000000u) : __uint_as_float(~k);
}

// ---------------------------------------------------------------------------
// Kernel 1: 3x3 NMS + top-50 per (batch, channel). One CTA per channel.
// Phase A: vectorized NMS (separable column-max), warp-aggregated compaction.
// Phase B: MSD radix-select (256-bin) to find top-50 threshold.
// Phase C: collect survivors >= threshold (<=512), exact top-50 by one warp
//          in registers with lax.top_k tie-break (value desc, index asc).
// ---------------------------------------------------------------------------
__global__ __launch_bounds__(512) void nms_topk_kernel(const float* __restrict__ heat){
    __shared__ unsigned ck[CAND_CAP];
    __shared__ int      ci[CAND_CAP];
    __shared__ unsigned hist[256];
    __shared__ unsigned sk[SBUF];
    __shared__ int      si[SBUF];
    __shared__ int cnt, scnt;
    __shared__ unsigned s_prefix;
    __shared__ int s_remaining, s_above, s_total;

    const int bc = blockIdx.x;
    const float* __restrict__ h = heat + (size_t)bc * NHW;
    const int t = threadIdx.x;
    const int lane = t & 31;

    if (t == 0){ cnt = 0; scnt = 0; s_prefix = 0u; s_remaining = K_TOP; s_above = 0; }
    __syncthreads();

    // ---- Phase A: NMS, 8 pixels per item --------------------------------
    #pragma unroll 1
    for (int it = 0; it < 8; it++){
        int item = it * 512 + t;
        if (item >= NITEMS) break;        // boundary is a multiple of 32 -> warp-uniform
        int y  = item / 40;               // 40 = NW/8
        int x0 = (item - y * 40) * 8;
        int yA = y > 0      ? y - 1 : 0;
        int yB = y < NH - 1 ? y + 1 : NH - 1;
        const float* r0 = h + yA * NW;
        const float* r1 = h + y  * NW;
        const float* r2 = h + yB * NW;
        float4 a0 = *(const float4*)(r0 + x0); float4 b0 = *(const float4*)(r0 + x0 + 4);
        float4 a1 = *(const float4*)(r1 + x0); float4 b1 = *(const float4*)(r1 + x0 + 4);
        float4 a2 = *(const float4*)(r2 + x0); float4 b2 = *(const float4*)(r2 + x0 + 4);
        float c[8] = {a1.x, a1.y, a1.z, a1.w, b1.x, b1.y, b1.z, b1.w};
        float vm[10];
        vm[1] = fmaxf(fmaxf(a0.x, a1.x), a2.x);
        vm[2] = fmaxf(fmaxf(a0.y, a1.y), a2.y);
        vm[3] = fmaxf(fmaxf(a0.z, a1.z), a2.z);
        vm[4] = fmaxf(fmaxf(a0.w, a1.w), a2.w);
        vm[5] = fmaxf(fmaxf(b0.x, b1.x), b2.x);
        vm[6] = fmaxf(fmaxf(b0.y, b1.y), b2.y);
        vm[7] = fmaxf(fmaxf(b0.z, b1.z), b2.z);
        vm[8] = fmaxf(fmaxf(b0.w, b1.w), b2.w);
        vm[0] = (x0 > 0)       ? fmaxf(fmaxf(r0[x0-1], r1[x0-1]), r2[x0-1]) : -1e30f;
        vm[9] = (x0 + 8 < NW)  ? fmaxf(fmaxf(r0[x0+8], r1[x0+8]), r2[x0+8]) : -1e30f;
        #pragma unroll
        for (int j = 0; j < 8; j++){
            float hm = fmaxf(fmaxf(vm[j], vm[j+1]), vm[j+2]);
            bool peak = (c[j] == hm);
            unsigned pm = __ballot_sync(0xFFFFFFFFu, peak);
            if (pm){
                int ldr = __ffs(pm) - 1;
                int base = 0;
                if (lane == ldr) base = atomicAdd(&cnt, __popc(pm));
                base = __shfl_sync(0xFFFFFFFFu, base, ldr);
                if (peak){
                    int p = base + __popc(pm & ((1u << lane) - 1u));
                    if (p < CAND_CAP){ ck[p] = f2k(c[j]); ci[p] = y * NW + x0 + j; }
                }
            }
        }
    }
    __syncthreads();
    int n = min(cnt, CAND_CAP);

    // ---- Phase B: MSD radix select --------------------------------------
    unsigned prefix = 0u;
    int shift = 24;
    #pragma unroll 1
    for (int pass = 0; pass < 4; pass++){
        if (t < 256) hist[t] = 0u;
        __syncthreads();
        for (int j = t; j < n; j += 512){
            unsigned key = ck[j];
            bool act = (pass == 0) || ((key >> (shift + 8)) == prefix);
            if (act) atomicAdd(&hist[(key >> shift) & 255u], 1u);
        }
        __syncthreads();
        if (t == 0){
            int rem = s_remaining;
            int cum = 0, d = 0;
            for (int dd = 255; dd >= 0; dd--){
                cum += (int)hist[dd];
                if (cum >= rem){ d = dd; break; }
            }
            int binc = (int)hist[d];
            int above_inc = cum - binc;
            s_total = s_above + cum;          // count matching final predicate
            s_above += above_inc;
            s_remaining = rem - above_inc;
            s_prefix = (s_prefix << 8) | (unsigned)d;
        }
        __syncthreads();
        prefix = s_prefix;
        if (s_total <= SBUF || shift == 0) break;
        shift -= 8;
    }

    // ---- Phase C: collect + exact top-50 by warp 0 ----------------------
    for (int j = t; j < n; j += 512){
        unsigned key = ck[j];
        if ((key >> shift) >= prefix){
            int p = atomicAdd(&scnt, 1);
            if (p < SBUF){ sk[p] = key; si[p] = ci[j]; }
        }
    }
    __syncthreads();

    if (t < 32){
        int m = min(scnt, SBUF);
        int R = (m + 31) >> 5;                 // elements per lane (<=16)
        unsigned kk[16]; int ii[16];
        for (int r = 0; r < R; r++){
            int j = lane + (r << 5);
            kk[r] = (j < m) ? sk[j] : 0u;
            ii[r] = (j < m) ? si[j] : 0x7FFFFFFF;
        }
        for (int k = 0; k < K_TOP; k++){
            unsigned bk = 0u; int bi = 0x7FFFFFFF; int br = -1;
            for (int r = 0; r < R; r++){
                if (kk[r] > bk || (kk[r] == bk && ii[r] < bi)){ bk = kk[r]; bi = ii[r]; br = r; }
            }
            unsigned lbk = bk; int lbi = bi;
            #pragma unroll
            for (int off = 16; off; off >>= 1){
                unsigned ok = __shfl_xor_sync(0xFFFFFFFFu, bk, off);
                int      oi = __shfl_xor_sync(0xFFFFFFFFu, bi, off);
                if (ok > bk || (ok == bk && oi < bi)){ bk = ok; bi = oi; }
            }
            if (br >= 0 && lbk == bk && lbi == bi){ kk[br] = 0u; ii[br] = 0x7FFFFFFF; }
            if (lane == 0){
                float v; int id;
                if (bk == 0u){ v = 0.0f; id = 0; }      // exhausted (never for this data)
                else         { v = k2f(bk); id = bi; }
                g_vals[bc * K_TOP + k] = v;
                g_inds[bc * K_TOP + k] = id;
            }
        }
    }
}

// ---------------------------------------------------------------------------
// Kernel 2: fused per-batch 3-way merge + per-detection geometry.
// One CTA per batch: thread 0 merges 3 sorted lists (tie -> lower channel,
// matching flat-index tie-break of ref top_k), then 50 threads do geometry.
// ---------------------------------------------------------------------------
__device__ __forceinline__ void inv3(const float* __restrict__ A, float* Ai){
    float a = A[0], b = A[1], c = A[2];
    float d = A[3], e = A[4], f = A[5];
    float g = A[6], h = A[7], i = A[8];
    float A00 = e*i - f*h, A01 = c*h - b*i, A02 = b*f - c*e;
    float A10 = f*g - d*i, A11 = a*i - c*g, A12 = c*d - a*f;
    float A20 = d*h - e*g, A21 = b*g - a*h, A22 = a*e - b*d;
    float r = 1.0f / (a*A00 + b*A10 + c*A20);
    Ai[0] = A00*r; Ai[1] = A01*r; Ai[2] = A02*r;
    Ai[3] = A10*r; Ai[4] = A11*r; Ai[5] = A12*r;
    Ai[6] = A20*r; Ai[7] = A21*r; Ai[8] = A22*r;
}

__device__ __forceinline__ float wrap_pi(float a){
    return a > PI_F ? a - 2.0f*PI_F : (a < -PI_F ? a + 2.0f*PI_F : a);
}

__global__ __launch_bounds__(64) void merge_geom_kernel(const float* __restrict__ regr,
                                                        const float* __restrict__ calib,
                                                        const float* __restrict__ trans,
                                                        const float* __restrict__ dimref,
                                                        float* __restrict__ out){
    __shared__ float s_score[K_TOP];
    __shared__ int   s_hw[K_TOP];
    __shared__ int   s_cls[K_TOP];
    const int b = blockIdx.x;
    const int t = threadIdx.x;

    if (t == 0){
        int j0 = 0, j1 = 0, j2 = 0;
        const float* base  = g_vals + b * NC * K_TOP;
        const int*   ibase = g_inds + b * NC * K_TOP;
        for (int k = 0; k < K_TOP; k++){
            float v0 = (j0 < K_TOP) ? base[0*K_TOP + j0] : -1e30f;
            float v1 = (j1 < K_TOP) ? base[1*K_TOP + j1] : -1e30f;
            float v2 = (j2 < K_TOP) ? base[2*K_TOP + j2] : -1e30f;
            int c = 0; float bv = v0;
            if (v1 > bv){ bv = v1; c = 1; }     // strict >: ties keep lower channel
            if (v2 > bv){ bv = v2; c = 2; }
            int jc = (c == 0) ? j0 : (c == 1 ? j1 : j2);
            s_score[k] = bv;
            s_cls[k]   = c;
            s_hw[k]    = ibase[c*K_TOP + jc];
            if (c == 0) j0++; else if (c == 1) j1++; else j2++;
        }
    }
    __syncthreads();
    if (t >= K_TOP) return;

    const int det = b * K_TOP + t;
    float score = s_score[t];
    float* o = out + (size_t)det * 14;

    if (!(score > DET_TH)){
        #pragma unroll
        for (int i = 0; i < 14; i++) o[i] = 0.0f;
        return;
    }

    int hw  = s_hw[t];
    int cls = s_cls[t];
    float xs = (float)(hw % NW);
    float ys = (float)(hw / NW);

    float reg[12];
    const float* rb = regr + ((size_t)b * 12) * NHW + hw;
    #pragma unroll
    for (int r = 0; r < 12; r++) reg[r] = __ldg(rb + r * NHW);

    float Ti[9], Ki[9], Tm[9], Km[9];
    #pragma unroll
    for (int i = 0; i < 9; i++){ Tm[i] = __ldg(trans + b*9 + i); Km[i] = __ldg(calib + b*9 + i); }
    inv3(Tm, Ti);
    inv3(Km, Ki);

    float depth = reg[0] * 16.32f + 28.01f;
    float px = xs + reg[1], py = ys + reg[2];
    float t0 = (Ti[0]*px + Ti[1]*py + Ti[2]) * depth;
    float t1 = (Ti[3]*px + Ti[4]*py + Ti[5]) * depth;
    float t2 = (Ti[6]*px + Ti[7]*py + Ti[8]) * depth;
    float l0 = Ki[0]*t0 + Ki[1]*t1 + Ki[2]*t2;
    float l1 = Ki[3]*t0 + Ki[4]*t1 + Ki[5]*t2;
    float l2 = Ki[6]*t0 + Ki[7]*t1 + Ki[8]*t2;

    float d0 = expf(reg[3]) * __ldg(dimref + cls*3 + 0);
    float d1 = expf(reg[4]) * __ldg(dimref + cls*3 + 1);
    float d2 = expf(reg[5]) * __ldg(dimref + cls*3 + 2);
    l1 += d1 * 0.5f;

    float ray   = atanf(l0 / (l2 + 1e-7f));
    float alpha = atanf(reg[6] / (reg[7] + 1e-7f));
    alpha += (reg[7] >= 0.0f) ? -PI_F*0.5f : PI_F*0.5f;
    float roty = wrap_pi(alpha + ray);     // pre-wrap alpha, per ref
    alpha = wrap_pi(alpha);

    float cx = xs + reg[8], cy = ys + reg[9];
    float ltx = cx - reg[10]*0.5f, lty = cy - reg[11]*0.5f;
    float rbx = cx + reg[10]*0.5f, rby = cy + reg[11]*0.5f;
    float b0 = Ti[0]*ltx + Ti[1]*lty + Ti[2];
    float b1 = Ti[3]*ltx + Ti[4]*lty + Ti[5];
    float b2 = Ti[0]*rbx + Ti[1]*rby + Ti[2];
    float b3 = Ti[3]*rbx + Ti[4]*rby + Ti[5];

    o[0]  = (float)cls;
    o[1]  = alpha;
    o[2]  = b0; o[3] = b1; o[4] = b2; o[5] = b3;
    o[6]  = d1; o[7] = d2; o[8] = d0;      // roll(dims3d, -1)
    o[9]  = l0; o[10] = l1; o[11] = l2;
    o[12] = roty;
    o[13] = score;
}

// ---------------------------------------------------------------------------
extern "C" void kernel_launch(void* const* d_in, const int* in_sizes, int n_in,
                              void* d_out, int out_size){
    const float* heat   = (const float*)d_in[0];
    const float* regr   = (const float*)d_in[1];
    const float* calib  = (const float*)d_in[2];
    const float* trans  = (const float*)d_in[3];
    const float* dimref = (const float*)d_in[4];
    float* out = (float*)d_out;

    nms_topk_kernel<<<NB * NC, 512>>>(heat);
    merge_geom_kernel<<<NB, 64>>>(regr, calib, trans, dimref, out);
}

// round 3
// speedup vs baseline: 5.1366x; 1.8889x over previous
#include <cuda_runtime.h>

#define NB 64
#define NC 3
#define NH 96
#define NW 320
#define NHW (NH*NW)
#define K_TOP 50
#define CAND_CAP 4864
#define SBUF 512
#define DET_TH 0.25f
#define PI_F 3.14159265f
#define NITEMS (NH*(NW/8))   // 3840 items of 8 pixels

typedef unsigned long long ull;

__device__ float g_vals[NB*NC*K_TOP];
__device__ int   g_inds[NB*NC*K_TOP];

// order-preserving float->uint key (ascending float -> ascending uint)
__device__ __forceinline__ unsigned f2k(float f){
    unsigned b = __float_as_uint(f);
    return (b & 0x80000000u) ? ~b : (b | 0x80000000u);
}
__device__ __forceinline__ float k2f(unsigned k){
    return (k & 0x80000000u) ? __uint_as_float(k ^ 0x80000000u) : __uint_as_float(~k);
}

// ---------------------------------------------------------------------------
// Kernel 1: 3x3 NMS + top-50 per (batch, channel). One CTA per channel.
// Candidates packed as (f2k(v)<<32)|~idx so pk-desc == (value desc, idx asc).
// Phase A: vectorized NMS, ONE shared atomic per warp-item (popc+scan).
// Phase B: MSD radix-select with match_any-aggregated histograms.
// Phase C: collect survivors (<=512), parallel exact rank, direct write.
// ---------------------------------------------------------------------------
__global__ __launch_bounds__(512) void nms_topk_kernel(const float* __restrict__ heat){
    __shared__ ull      ck[CAND_CAP];
    __shared__ ull      sk[SBUF];
    __shared__ unsigned hist[256];
    __shared__ int cnt, scnt;
    __shared__ unsigned s_prefix;
    __shared__ int s_remaining, s_total;

    const int bc = blockIdx.x;
    const float* __restrict__ h = heat + (size_t)bc * NHW;
    const int t = threadIdx.x;
    const int lane = t & 31;

    if (t == 0){ cnt = 0; scnt = 0; s_prefix = 0u; s_remaining = K_TOP; s_total = 0; }
    __syncthreads();

    // ---- Phase A: NMS, 8 pixels per item, 1 atomic per warp-item --------
    #pragma unroll 1
    for (int it = 0; it < 8; it++){
        int item = it * 512 + t;
        if (item >= NITEMS) break;        // boundary warp-uniform (t>=256 @ it=7)
        int y  = item / 40;               // 40 = NW/8
        int x0 = (item - y * 40) * 8;
        int yA = y > 0      ? y - 1 : 0;
        int yB = y < NH - 1 ? y + 1 : NH - 1;
        const float* r0 = h + yA * NW;
        const float* r1 = h + y  * NW;
        const float* r2 = h + yB * NW;
        float4 a0 = *(const float4*)(r0 + x0); float4 b0 = *(const float4*)(r0 + x0 + 4);
        float4 a1 = *(const float4*)(r1 + x0); float4 b1 = *(const float4*)(r1 + x0 + 4);
        float4 a2 = *(const float4*)(r2 + x0); float4 b2 = *(const float4*)(r2 + x0 + 4);
        float c[8] = {a1.x, a1.y, a1.z, a1.w, b1.x, b1.y, b1.z, b1.w};
        float vm[10];
        vm[1] = fmaxf(fmaxf(a0.x, a1.x), a2.x);
        vm[2] = fmaxf(fmaxf(a0.y, a1.y), a2.y);
        vm[3] = fmaxf(fmaxf(a0.z, a1.z), a2.z);
        vm[4] = fmaxf(fmaxf(a0.w, a1.w), a2.w);
        vm[5] = fmaxf(fmaxf(b0.x, b1.x), b2.x);
        vm[6] = fmaxf(fmaxf(b0.y, b1.y), b2.y);
        vm[7] = fmaxf(fmaxf(b0.z, b1.z), b2.z);
        vm[8] = fmaxf(fmaxf(b0.w, b1.w), b2.w);
        vm[0] = (x0 > 0)      ? fmaxf(fmaxf(r0[x0-1], r1[x0-1]), r2[x0-1]) : -1e30f;
        vm[9] = (x0 + 8 < NW) ? fmaxf(fmaxf(r0[x0+8], r1[x0+8]), r2[x0+8]) : -1e30f;

        unsigned msk = 0u;
        #pragma unroll
        for (int j = 0; j < 8; j++){
            float hm = fmaxf(fmaxf(vm[j], vm[j+1]), vm[j+2]);
            if (c[j] == hm) msk |= (1u << j);
        }
        int cl  = __popc(msk);
        int inc = cl;                       // warp inclusive scan of counts
        #pragma unroll
        for (int d = 1; d < 32; d <<= 1){
            int v = __shfl_up_sync(0xFFFFFFFFu, inc, d);
            if (lane >= d) inc += v;
        }
        int tot = __shfl_sync(0xFFFFFFFFu, inc, 31);
        if (tot){
            int base = 0;
            if (lane == 31) base = atomicAdd(&cnt, tot);
            base = __shfl_sync(0xFFFFFFFFu, base, 31);
            int pos = base + inc - cl;
            while (msk){
                int j = __ffs(msk) - 1; msk &= msk - 1;
                if (pos < CAND_CAP)
                    ck[pos] = ((ull)f2k(c[j]) << 32) | (unsigned)~(y * NW + x0 + j);
                pos++;
            }
        }
    }
    __syncthreads();
    int n  = min(cnt, CAND_CAP);
    int np = (n + 511) & ~511;              // padded trips: full warps active

    // ---- Phase B: MSD radix select (warp-aggregated histogram) ----------
    unsigned prefix = 0u;
    int shift = 24;
    #pragma unroll 1
    for (int pass = 0; pass < 4; pass++){
        if (t < 256) hist[t] = 0u;
        __syncthreads();
        for (int j = t; j < np; j += 512){
            bool act = (j < n);
            unsigned d = 0xFFFFFFFFu;
            if (act){
                unsigned key = (unsigned)(ck[j] >> 32);
                act = (pass == 0) || ((key >> (shift + 8)) == prefix);
                if (act) d = (key >> shift) & 255u;
            }
            unsigned peers = __match_any_sync(0xFFFFFFFFu, d);
            if (act && ((int)lane == __ffs(peers) - 1))
                atomicAdd(&hist[d], __popc(peers));
        }
        __syncthreads();
        if (t == 0){
            int rem = s_remaining;
            int cum = 0, d = 255;
            for (int dd = 255; dd >= 0; dd--){
                cum += (int)hist[dd];
                if (cum >= rem){ d = dd; break; }
            }
            int above_inc = cum - (int)hist[d];
            s_total     = (K_TOP - rem) + cum;   // keys matching final predicate
            s_remaining = rem - above_inc;
            s_prefix    = (s_prefix << 8) | (unsigned)d;
        }
        __syncthreads();
        prefix = s_prefix;
        if (s_total <= SBUF || shift == 0) break;
        shift -= 8;
    }

    // ---- Phase C: collect + parallel exact rank -------------------------
    if (t < K_TOP){ g_vals[bc * K_TOP + t] = 0.0f; g_inds[bc * K_TOP + t] = 0; }
    for (int j = t; j < n; j += 512){
        ull p = ck[j];
        if (((unsigned)(p >> 32) >> shift) >= prefix){
            int q = atomicAdd(&scnt, 1);
            if (q < SBUF) sk[q] = p;
        }
    }
    __syncthreads();
    int m = min(scnt, SBUF);
    if (t < m){
        ull mine = sk[t];
        int r = 0;
        for (int jj = 0; jj < m; jj++) r += (sk[jj] > mine);   // broadcast reads
        if (r < K_TOP){
            g_vals[bc * K_TOP + r] = k2f((unsigned)(mine >> 32));
            g_inds[bc * K_TOP + r] = (int)~((unsigned)mine);
        }
    }
}

// ---------------------------------------------------------------------------
// Kernel 2: fused per-batch parallel 3-way merge + per-detection geometry.
// Element (c,j): merged rank = j + sum_{c2!=c}[ cnt(v2>v) + (c2<c)*cnt(v2==v) ]
// == lax.top_k order over the concatenated (C*TOPK) array (flat-index ties).
// ---------------------------------------------------------------------------
__device__ __forceinline__ void inv3(const float* __restrict__ A, float* Ai){
    float a = A[0], b = A[1], c = A[2];
    float d = A[3], e = A[4], f = A[5];
    float g = A[6], h = A[7], i = A[8];
    float A00 = e*i - f*h, A01 = c*h - b*i, A02 = b*f - c*e;
    float A10 = f*g - d*i, A11 = a*i - c*g, A12 = c*d - a*f;
    float A20 = d*h - e*g, A21 = b*g - a*h, A22 = a*e - b*d;
    float r = 1.0f / (a*A00 + b*A10 + c*A20);
    Ai[0] = A00*r; Ai[1] = A01*r; Ai[2] = A02*r;
    Ai[3] = A10*r; Ai[4] = A11*r; Ai[5] = A12*r;
    Ai[6] = A20*r; Ai[7] = A21*r; Ai[8] = A22*r;
}

__device__ __forceinline__ float wrap_pi(float a){
    return a > PI_F ? a - 2.0f*PI_F : (a < -PI_F ? a + 2.0f*PI_F : a);
}

__global__ __launch_bounds__(192) void merge_geom_kernel(const float* __restrict__ regr,
                                                         const float* __restrict__ calib,
                                                         const float* __restrict__ trans,
                                                         const float* __restrict__ dimref,
                                                         float* __restrict__ out){
    __shared__ float mv[NC*K_TOP];
    __shared__ int   mi[NC*K_TOP];
    __shared__ float s_score[K_TOP];
    __shared__ int   s_hw[K_TOP];
    __shared__ int   s_cls[K_TOP];
    const int b = blockIdx.x;
    const int t = threadIdx.x;

    if (t < NC*K_TOP){
        mv[t] = g_vals[b * NC * K_TOP + t];
        mi[t] = g_inds[b * NC * K_TOP + t];
    }
    __syncthreads();

    if (t < NC*K_TOP){
        int c = t / K_TOP, j = t - c * K_TOP;
        float v = mv[t];
        int rank = j;
        #pragma unroll
        for (int c2 = 0; c2 < NC; c2++){
            if (c2 == c) continue;
            const float* o2 = mv + c2 * K_TOP;
            int cg = 0, ce = 0;
            #pragma unroll 10
            for (int jj = 0; jj < K_TOP; jj++){
                float v2 = o2[jj];
                cg += (v2 > v);
                ce += (v2 == v);
            }
            rank += cg + ((c2 < c) ? ce : 0);
        }
        if (rank < K_TOP){
            s_score[rank] = v;
            s_hw[rank]    = mi[t];
            s_cls[rank]   = c;
        }
    }
    __syncthreads();

    if (t < K_TOP){
        const int det = b * K_TOP + t;
        float score = s_score[t];
        float* o = out + (size_t)det * 14;

        if (!(score > DET_TH)){
            #pragma unroll
            for (int i = 0; i < 14; i++) o[i] = 0.0f;
        } else {
            int hw  = s_hw[t];
            int cls = s_cls[t];
            float xs = (float)(hw % NW);
            float ys = (float)(hw / NW);

            float reg[12];
            const float* rb = regr + ((size_t)b * 12) * NHW + hw;
            #pragma unroll
            for (int r = 0; r < 12; r++) reg[r] = __ldg(rb + r * NHW);

            float Ti[9], Ki[9], Tm[9], Km[9];
            #pragma unroll
            for (int i = 0; i < 9; i++){ Tm[i] = __ldg(trans + b*9 + i); Km[i] = __ldg(calib + b*9 + i); }
            inv3(Tm, Ti);
            inv3(Km, Ki);

            float depth = reg[0] * 16.32f + 28.01f;
            float px = xs + reg[1], py = ys + reg[2];
            float t0 = (Ti[0]*px + Ti[1]*py + Ti[2]) * depth;
            float t1 = (Ti[3]*px + Ti[4]*py + Ti[5]) * depth;
            float t2 = (Ti[6]*px + Ti[7]*py + Ti[8]) * depth;
            float l0 = Ki[0]*t0 + Ki[1]*t1 + Ki[2]*t2;
            float l1 = Ki[3]*t0 + Ki[4]*t1 + Ki[5]*t2;
            float l2 = Ki[6]*t0 + Ki[7]*t1 + Ki[8]*t2;

            float d0 = expf(reg[3]) * __ldg(dimref + cls*3 + 0);
            float d1 = expf(reg[4]) * __ldg(dimref + cls*3 + 1);
            float d2 = expf(reg[5]) * __ldg(dimref + cls*3 + 2);
            l1 += d1 * 0.5f;

            float ray   = atanf(l0 / (l2 + 1e-7f));
            float alpha = atanf(reg[6] / (reg[7] + 1e-7f));
            alpha += (reg[7] >= 0.0f) ? -PI_F*0.5f : PI_F*0.5f;
            float roty = wrap_pi(alpha + ray);     // pre-wrap alpha, per ref
            alpha = wrap_pi(alpha);

            float cx = xs + reg[8], cy = ys + reg[9];
            float ltx = cx - reg[10]*0.5f, lty = cy - reg[11]*0.5f;
            float rbx = cx + reg[10]*0.5f, rby = cy + reg[11]*0.5f;
            float b0 = Ti[0]*ltx + Ti[1]*lty + Ti[2];
            float b1 = Ti[3]*ltx + Ti[4]*lty + Ti[5];
            float b2 = Ti[0]*rbx + Ti[1]*rby + Ti[2];
            float b3 = Ti[3]*rbx + Ti[4]*rby + Ti[5];

            o[0]  = (float)cls;
            o[1]  = alpha;
            o[2]  = b0; o[3] = b1; o[4] = b2; o[5] = b3;
            o[6]  = d1; o[7] = d2; o[8] = d0;      // roll(dims3d, -1)
            o[9]  = l0; o[10] = l1; o[11] = l2;
            o[12] = roty;
            o[13] = score;
        }
    }
}

// ---------------------------------------------------------------------------
extern "C" void kernel_launch(void* const* d_in, const int* in_sizes, int n_in,
                              void* d_out, int out_size){
    const float* heat   = (const float*)d_in[0];
    const float* regr   = (const float*)d_in[1];
    const float* calib  = (const float*)d_in[2];
    const float* trans  = (const float*)d_in[3];
    const float* dimref = (const float*)d_in[4];
    float* out = (float*)d_out;

    nms_topk_kernel<<<NB * NC, 512>>>(heat);
    merge_geom_kernel<<<NB, 192>>>(regr, calib, trans, dimref, out);
}

// round 5
// speedup vs baseline: 9.2458x; 1.8000x over previous
#include <cuda_runtime.h>

#define NB 64
#define NC 3
#define NH 96
#define NW 320
#define NHW (NH*NW)
#define K_TOP 50
#define CAND_CAP 4608
#define DIRECT_MAX 1024
#define SBUF 512
#define THETA 0.99f
#define DET_TH 0.25f
#define PI_F 3.14159265f
#define NSTRIPS (NH*(NW/8))   // 3840 strips of 8 pixels

typedef unsigned long long ull;

// one packed u64 per (channel, rank): (f2k(value)<<32) | ~pixel_idx
__device__ ull g_pk[NB*NC*K_TOP];

// order-preserving float->uint key (ascending float -> ascending uint)
__device__ __forceinline__ unsigned f2k(float f){
    unsigned b = __float_as_uint(f);
    return (b & 0x80000000u) ? ~b : (b | 0x80000000u);
}
__device__ __forceinline__ float k2f(unsigned k){
    return (k & 0x80000000u) ? __uint_as_float(k ^ 0x80000000u) : __uint_as_float(~k);
}

// ---------------------------------------------------------------------------
// Kernel 1: screened 3x3 NMS + exact top-50 per (batch, channel).
// Screen: strip max8 > THETA -> full 3x3 test only on ~8% of strips.
// Guard: found set == {peaks > THETA}; true top-50 contained iff cnt >= 50,
// else rerun unscreened (never taken for this data, keeps correctness).
// Select: direct exact rank if <=1024 candidates, radix-select fallback else.
// Per-channel rank uses full packed key == (value desc, pixel idx asc),
// identical to lax.top_k stage 1.
// ---------------------------------------------------------------------------
__global__ __launch_bounds__(512) void nms_topk_kernel(const float* __restrict__ heat){
    __shared__ ull      ck[CAND_CAP];
    __shared__ ull      sk[SBUF];
    __shared__ unsigned hist[256];
    __shared__ int cnt, scnt;
    __shared__ unsigned s_prefix;
    __shared__ int s_remaining, s_total;

    const int bc = blockIdx.x;
    const float* __restrict__ h = heat + (size_t)bc * NHW;
    const int t = threadIdx.x;

    if (t == 0){ cnt = 0; scnt = 0; s_prefix = 0u; s_remaining = K_TOP; s_total = 0; }
    __syncthreads();

    #pragma unroll 1
    for (int attempt = 0; attempt < 2; attempt++){
        const float theta = (attempt == 0) ? THETA : -1e30f;
        #pragma unroll 1
        for (int item = t; item < NSTRIPS; item += 512){
            int y  = item / 40;                 // 40 = NW/8
            int x0 = (item - y * 40) * 8;
            const float* r1 = h + y * NW;
            float4 a1 = *(const float4*)(r1 + x0);
            float4 b1 = *(const float4*)(r1 + x0 + 4);
            float m8 = fmaxf(fmaxf(fmaxf(a1.x, a1.y), fmaxf(a1.z, a1.w)),
                             fmaxf(fmaxf(b1.x, b1.y), fmaxf(b1.z, b1.w)));
            unsigned msk = 0u;
            if (m8 > theta){
                int yA = y > 0      ? y - 1 : 0;
                int yB = y < NH - 1 ? y + 1 : NH - 1;
                const float* r0 = h + yA * NW;
                const float* r2 = h + yB * NW;
                float4 a0 = *(const float4*)(r0 + x0); float4 b0 = *(const float4*)(r0 + x0 + 4);
                float4 a2 = *(const float4*)(r2 + x0); float4 b2 = *(const float4*)(r2 + x0 + 4);
                float c[8] = {a1.x, a1.y, a1.z, a1.w, b1.x, b1.y, b1.z, b1.w};
                float vm[10];
                vm[1] = fmaxf(fmaxf(a0.x, a1.x), a2.x);
                vm[2] = fmaxf(fmaxf(a0.y, a1.y), a2.y);
                vm[3] = fmaxf(fmaxf(a0.z, a1.z), a2.z);
                vm[4] = fmaxf(fmaxf(a0.w, a1.w), a2.w);
                vm[5] = fmaxf(fmaxf(b0.x, b1.x), b2.x);
                vm[6] = fmaxf(fmaxf(b0.y, b1.y), b2.y);
                vm[7] = fmaxf(fmaxf(b0.z, b1.z), b2.z);
                vm[8] = fmaxf(fmaxf(b0.w, b1.w), b2.w);
                vm[0] = (x0 > 0)      ? fmaxf(fmaxf(r0[x0-1], r1[x0-1]), r2[x0-1]) : -1e30f;
                vm[9] = (x0 + 8 < NW) ? fmaxf(fmaxf(r0[x0+8], r1[x0+8]), r2[x0+8]) : -1e30f;
                #pragma unroll
                for (int j = 0; j < 8; j++){
                    float hm = fmaxf(fmaxf(vm[j], vm[j+1]), vm[j+2]);
                    if (c[j] == hm && c[j] > theta) msk |= (1u << j);
                }
            }
            if (msk){
                int pos = atomicAdd(&cnt, __popc(msk));
                int base = y * NW + x0;
                while (msk){
                    int j = __ffs(msk) - 1; msk &= msk - 1;
                    if (pos < CAND_CAP)
                        ck[pos] = ((ull)f2k(h[base + j]) << 32) | (unsigned)~(base + j);
                    pos++;
                }
            }
        }
        __syncthreads();
        if (cnt >= K_TOP) break;      // guard: screened set provably contains top-50
        if (t == 0) cnt = 0;          // fallback: unscreened rescan
        __syncthreads();
    }

    int n = min(cnt, CAND_CAP);
    const ull* src = ck;
    int m = n;

    if (n > DIRECT_MAX){
        // ---- radix-select fallback (rare) -------------------------------
        unsigned prefix = 0u;
        int shift = 24;
        #pragma unroll 1
        for (int pass = 0; pass < 4; pass++){
            if (t < 256) hist[t] = 0u;
            __syncthreads();
            for (int j = t; j < n; j += 512){
                unsigned key = (unsigned)(ck[j] >> 32);
                bool act = (pass == 0) || ((key >> (shift + 8)) == prefix);
                if (act) atomicAdd(&hist[(key >> shift) & 255u], 1u);
            }
            __syncthreads();
            if (t == 0){
                int rem = s_remaining;
                int cum = 0, d = 255;
                for (int dd = 255; dd >= 0; dd--){
                    cum += (int)hist[dd];
                    if (cum >= rem){ d = dd; break; }
                }
                int above_inc = cum - (int)hist[d];
                s_total     = (K_TOP - rem) + cum;
                s_remaining = rem - above_inc;
                s_prefix    = (s_prefix << 8) | (unsigned)d;
            }
            __syncthreads();
            prefix = s_prefix;
            if (s_total <= SBUF || shift == 0) break;
            shift -= 8;
        }
        for (int j = t; j < n; j += 512){
            ull p = ck[j];
            if (((unsigned)(p >> 32) >> shift) >= prefix){
                int q = atomicAdd(&scnt, 1);
                if (q < SBUF) sk[q] = p;
            }
        }
        __syncthreads();
        src = sk; m = min(scnt, SBUF);
    }

    // pad output slots, then exact parallel rank (value desc, idx asc)
    if (t < K_TOP) g_pk[bc * K_TOP + t] = ((ull)0x80000000u << 32) | 0xFFFFFFFFull;
    __syncthreads();
    for (int i = t; i < m; i += 512){
        ull mine = src[i];
        int r = 0;
        for (int jj = 0; jj < m; jj++) r += (src[jj] > mine);   // smem broadcast
        if (r < K_TOP) g_pk[bc * K_TOP + r] = mine;
    }
}

// ---------------------------------------------------------------------------
// Kernel 2: per-batch parallel 3-way rank-merge + per-detection geometry.
// RANK ON VALUE ONLY (high 32 bits); ties -> lower flat position jj in the
// channel-major (C*TOPK) array == lax.top_k stage-2 tie-break. (R4 bug was
// ranking on the full packed key, which tie-broke by pixel idx instead.)
// ---------------------------------------------------------------------------
__device__ __forceinline__ void inv3(const float* __restrict__ A, float* Ai){
    float a = A[0], b = A[1], c = A[2];
    float d = A[3], e = A[4], f = A[5];
    float g = A[6], h = A[7], i = A[8];
    float A00 = e*i - f*h, A01 = c*h - b*i, A02 = b*f - c*e;
    float A10 = f*g - d*i, A11 = a*i - c*g, A12 = c*d - a*f;
    float A20 = d*h - e*g, A21 = b*g - a*h, A22 = a*e - b*d;
    float r = 1.0f / (a*A00 + b*A10 + c*A20);
    Ai[0] = A00*r; Ai[1] = A01*r; Ai[2] = A02*r;
    Ai[3] = A10*r; Ai[4] = A11*r; Ai[5] = A12*r;
    Ai[6] = A20*r; Ai[7] = A21*r; Ai[8] = A22*r;
}

__device__ __forceinline__ float wrap_pi(float a){
    return a > PI_F ? a - 2.0f*PI_F : (a < -PI_F ? a + 2.0f*PI_F : a);
}

__global__ __launch_bounds__(160) void merge_geom_kernel(const float* __restrict__ regr,
                                                         const float* __restrict__ calib,
                                                         const float* __restrict__ trans,
                                                         const float* __restrict__ dimref,
                                                         float* __restrict__ out){
    __shared__ ull spk[NC*K_TOP];
    __shared__ ull rpk[K_TOP];     // ranked: (key<<32)|(cls<<20)|idx
    const int b = blockIdx.x;
    const int t = threadIdx.x;

    if (t < NC*K_TOP) spk[t] = g_pk[b * NC * K_TOP + t];
    __syncthreads();

    if (t < NC*K_TOP){
        ull mine = spk[t];
        unsigned mk = (unsigned)(mine >> 32);      // value key only
        int r = 0;
        #pragma unroll 10
        for (int jj = 0; jj < NC*K_TOP; jj++){
            unsigned ok = (unsigned)(spk[jj] >> 32);
            r += (ok > mk) || (ok == mk && jj < t);  // flat-position tie-break
        }
        if (r < K_TOP){
            int cls = t / K_TOP;
            unsigned idx = ~((unsigned)mine);          // pixel index (< 2^20)
            rpk[r] = ((ull)mk << 32) | ((unsigned)cls << 20) | idx;
        }
    }
    __syncthreads();

    if (t < K_TOP){
        const int det = b * K_TOP + t;
        ull p = rpk[t];
        float score = k2f((unsigned)(p >> 32));
        float* o = out + (size_t)det * 14;

        if (!(score > DET_TH)){
            #pragma unroll
            for (int i = 0; i < 14; i++) o[i] = 0.0f;
        } else {
            int cls = (int)((p >> 20) & 3u);
            int hw  = (int)(p & 0xFFFFFu);
            float xs = (float)(hw % NW);
            float ys = (float)(hw / NW);

            float reg[12];
            const float* rb = regr + ((size_t)b * 12) * NHW + hw;
            #pragma unroll
            for (int r = 0; r < 12; r++) reg[r] = __ldg(rb + r * NHW);

            float Ti[9], Ki[9], Tm[9], Km[9];
            #pragma unroll
            for (int i = 0; i < 9; i++){ Tm[i] = __ldg(trans + b*9 + i); Km[i] = __ldg(calib + b*9 + i); }
            inv3(Tm, Ti);
            inv3(Km, Ki);

            float depth = reg[0] * 16.32f + 28.01f;
            float px = xs + reg[1], py = ys + reg[2];
            float t0 = (Ti[0]*px + Ti[1]*py + Ti[2]) * depth;
            float t1 = (Ti[3]*px + Ti[4]*py + Ti[5]) * depth;
            float t2 = (Ti[6]*px + Ti[7]*py + Ti[8]) * depth;
            float l0 = Ki[0]*t0 + Ki[1]*t1 + Ki[2]*t2;
            float l1 = Ki[3]*t0 + Ki[4]*t1 + Ki[5]*t2;
            float l2 = Ki[6]*t0 + Ki[7]*t1 + Ki[8]*t2;

            float d0 = expf(reg[3]) * __ldg(dimref + cls*3 + 0);
            float d1 = expf(reg[4]) * __ldg(dimref + cls*3 + 1);
            float d2 = expf(reg[5]) * __ldg(dimref + cls*3 + 2);
            l1 += d1 * 0.5f;

            float ray   = atanf(l0 / (l2 + 1e-7f));
            float alpha = atanf(reg[6] / (reg[7] + 1e-7f));
            alpha += (reg[7] >= 0.0f) ? -PI_F*0.5f : PI_F*0.5f;
            float roty = wrap_pi(alpha + ray);     // pre-wrap alpha, per ref
            alpha = wrap_pi(alpha);

            float cx = xs + reg[8], cy = ys + reg[9];
            float ltx = cx - reg[10]*0.5f, lty = cy - reg[11]*0.5f;
            float rbx = cx + reg[10]*0.5f, rby = cy + reg[11]*0.5f;
            float b0 = Ti[0]*ltx + Ti[1]*lty + Ti[2];
            float b1 = Ti[3]*ltx + Ti[4]*lty + Ti[5];
            float b2 = Ti[0]*rbx + Ti[1]*rby + Ti[2];
            float b3 = Ti[3]*rbx + Ti[4]*rby + Ti[5];

            o[0]  = (float)cls;
            o[1]  = alpha;
            o[2]  = b0; o[3] = b1; o[4] = b2; o[5] = b3;
            o[6]  = d1; o[7] = d2; o[8] = d0;      // roll(dims3d, -1)
            o[9]  = l0; o[10] = l1; o[11] = l2;
            o[12] = roty;
            o[13] = score;
        }
    }
}

// ---------------------------------------------------------------------------
extern "C" void kernel_launch(void* const* d_in, const int* in_sizes, int n_in,
                              void* d_out, int out_size){
    const float* heat   = (const float*)d_in[0];
    const float* regr   = (const float*)d_in[1];
    const float* calib  = (const float*)d_in[2];
    const float* trans  = (const float*)d_in[3];
    const float* dimref = (const float*)d_in[4];
    float* out = (float*)d_out;

    nms_topk_kernel<<<NB * NC, 512>>>(heat);
    merge_geom_kernel<<<NB, 160>>>(regr, calib, trans, dimref, out);
}